// round 2
// baseline (speedup 1.0000x reference)
#include <cuda_runtime.h>
#include <cuda_bf16.h>

#define Bsz 8
#define Nn 2048
#define FIN 128
#define FO 64
#define ALPHA 0.2f
#define NEG_INF -9000000000000000.0f

#define BM 64
#define BN 64
#define SP_PITCH (BN + 4)

// Scratch (device globals: allocation-free per harness rules)
__device__ float g_Wh[Bsz * Nn * FO];        // 4 MB
__device__ float g_e1[Bsz * Nn];
__device__ float g_e2[Bsz * Nn];

// ---------------------------------------------------------------------------
// Kernel 1: Wh = h @ W ; e1 = Wh·a1 ; e2 = Wh·a2
// 256 threads = 8 warps, 2 rows per warp -> 16 rows/block, 1024 blocks.
// ---------------------------------------------------------------------------
__global__ __launch_bounds__(256) void gat_proj_kernel(
    const float* __restrict__ h,
    const float* __restrict__ W,
    const float* __restrict__ a)
{
    __shared__ float sW[FIN * FO];   // 32 KB

    const int t = threadIdx.x;
    // cooperative W load (8192 floats)
#pragma unroll
    for (int r = 0; r < 8; r++) {
        *(float4*)&sW[r * 1024 + t * 4] = *(const float4*)&W[r * 1024 + t * 4];
    }

    const int warp = t >> 5;
    const int lane = t & 31;
    const int i0 = blockIdx.x * 16 + warp * 2;   // two rows: i0, i0+1

    const float a1l = a[lane];
    const float a1h = a[lane + 32];
    const float a2l = a[FO + lane];
    const float a2h = a[FO + 32 + lane];

    __syncthreads();

    // stage h rows in registers
    float hr0[4], hr1[4];
    const float* h0p = h + (long)i0 * FIN;
    const float* h1p = h + (long)(i0 + 1) * FIN;
#pragma unroll
    for (int q = 0; q < 4; q++) {
        hr0[q] = h0p[q * 32 + lane];
        hr1[q] = h1p[q * 32 + lane];
    }

    float acc00 = 0.f, acc01 = 0.f, acc10 = 0.f, acc11 = 0.f;
#pragma unroll
    for (int q = 0; q < 4; q++) {
#pragma unroll
        for (int kk = 0; kk < 32; kk++) {
            const int k = q * 32 + kk;
            const float w0 = sW[k * FO + lane];
            const float w1 = sW[k * FO + 32 + lane];
            const float hv0 = __shfl_sync(0xffffffffu, hr0[q], kk);
            const float hv1 = __shfl_sync(0xffffffffu, hr1[q], kk);
            acc00 = fmaf(hv0, w0, acc00);
            acc01 = fmaf(hv0, w1, acc01);
            acc10 = fmaf(hv1, w0, acc10);
            acc11 = fmaf(hv1, w1, acc11);
        }
    }

    // write Wh
    g_Wh[(long)i0 * FO + lane]            = acc00;
    g_Wh[(long)i0 * FO + 32 + lane]       = acc01;
    g_Wh[(long)(i0 + 1) * FO + lane]      = acc10;
    g_Wh[(long)(i0 + 1) * FO + 32 + lane] = acc11;

    // e1/e2 via warp reduction
    float e1a = acc00 * a1l + acc01 * a1h;
    float e2a = acc00 * a2l + acc01 * a2h;
    float e1b = acc10 * a1l + acc11 * a1h;
    float e2b = acc10 * a2l + acc11 * a2h;
#pragma unroll
    for (int off = 16; off > 0; off >>= 1) {
        e1a += __shfl_xor_sync(0xffffffffu, e1a, off);
        e2a += __shfl_xor_sync(0xffffffffu, e2a, off);
        e1b += __shfl_xor_sync(0xffffffffu, e1b, off);
        e2b += __shfl_xor_sync(0xffffffffu, e2b, off);
    }
    if (lane == 0) {
        g_e1[i0]     = e1a;
        g_e2[i0]     = e2a;
        g_e1[i0 + 1] = e1b;
        g_e2[i0 + 1] = e2b;
    }
}

// ---------------------------------------------------------------------------
// Kernel 2: flash-style masked-softmax aggregation.
// grid = (N/BM, B) = (32, 8); block = 256 threads.
// Online softmax with per-row rescale; register-tiled 4x4 fp32 P·V matmul.
// ---------------------------------------------------------------------------
__global__ __launch_bounds__(256) void gat_agg_kernel(
    const int* __restrict__ adj,
    float* __restrict__ out)
{
    __shared__ float sV[BN][FO];          // 16 KB  (Wh j-tile)
    __shared__ float sP[BM][SP_PITCH];    // ~17 KB (probability tile)
    __shared__ float sE1[BM];
    __shared__ float sM[BM];
    __shared__ float sS[BM];
    __shared__ float sScale[BM];

    const int b  = blockIdx.y;
    const int i0 = blockIdx.x * BM;
    const int t  = threadIdx.x;
    const int tx = t & 15;         // matmul col group
    const int ty = t >> 4;         // matmul row group
    const int rowi = t >> 2;       // P-compute row (0..63)
    const int q    = t & 3;        // P-compute j-quarter

    if (t < BM) {
        sE1[t] = g_e1[b * Nn + i0 + t];
        sM[t]  = NEG_INF;
        sS[t]  = 0.f;
        sScale[t] = 1.f;
    }

    float acc[4][4];
#pragma unroll
    for (int r = 0; r < 4; r++)
#pragma unroll
        for (int c = 0; c < 4; c++) acc[r][c] = 0.f;

    const float* e2p = g_e2 + b * Nn;
    const int*  adjRow = adj + ((long)(b * Nn + i0 + rowi)) * Nn;

    __syncthreads();

    for (int j0 = 0; j0 < Nn; j0 += BN) {
        // ---- load Wh tile (coalesced float4) ----
#pragma unroll
        for (int r = 0; r < 4; r++) {
            const int idx = r * 1024 + t * 4;       // 0..4095
            const int jj = idx >> 6, c = idx & 63;
            *(float4*)&sV[jj][c] =
                *(const float4*)&g_Wh[((long)(b * Nn + j0 + jj)) * FO + c];
        }

        // ---- compute masked/lrelu scores for 16 j's ----
        const int jb = j0 + (q << 4);
        const float e1i = sE1[rowi];
        float ev[16];
        float lm = NEG_INF;
#pragma unroll
        for (int k4 = 0; k4 < 4; k4++) {
            const int4  av  = *(const int4*)(adjRow + jb + (k4 << 2));
            const float4 e2v = *(const float4*)(e2p + jb + (k4 << 2));
            float x;
            x = e1i + e2v.x; x = fmaxf(x, ALPHA * x); x = (av.x > 0) ? x : NEG_INF;
            ev[(k4 << 2) + 0] = x; lm = fmaxf(lm, x);
            x = e1i + e2v.y; x = fmaxf(x, ALPHA * x); x = (av.y > 0) ? x : NEG_INF;
            ev[(k4 << 2) + 1] = x; lm = fmaxf(lm, x);
            x = e1i + e2v.z; x = fmaxf(x, ALPHA * x); x = (av.z > 0) ? x : NEG_INF;
            ev[(k4 << 2) + 2] = x; lm = fmaxf(lm, x);
            x = e1i + e2v.w; x = fmaxf(x, ALPHA * x); x = (av.w > 0) ? x : NEG_INF;
            ev[(k4 << 2) + 3] = x; lm = fmaxf(lm, x);
        }
        // row max across the 4 cooperating threads (same warp, lanes 4i..4i+3)
        lm = fmaxf(lm, __shfl_xor_sync(0xffffffffu, lm, 1));
        lm = fmaxf(lm, __shfl_xor_sync(0xffffffffu, lm, 2));

        const float mOld = sM[rowi];
        const float mNew = fmaxf(mOld, lm);

        float ls = 0.f;
#pragma unroll
        for (int k = 0; k < 16; k++) {
            const float p = __expf(ev[k] - mNew);
            ev[k] = p;
            ls += p;
        }
        ls += __shfl_xor_sync(0xffffffffu, ls, 1);
        ls += __shfl_xor_sync(0xffffffffu, ls, 2);

        if (q == 0) {
            const float scale = __expf(mOld - mNew);
            sS[rowi] = sS[rowi] * scale + ls;
            sM[rowi] = mNew;
            sScale[rowi] = scale;
        }

        // store P tile
#pragma unroll
        for (int k4 = 0; k4 < 4; k4++) {
            float4 pv = make_float4(ev[(k4 << 2) + 0], ev[(k4 << 2) + 1],
                                    ev[(k4 << 2) + 2], ev[(k4 << 2) + 3]);
            *(float4*)&sP[rowi][(q << 4) + (k4 << 2)] = pv;
        }

        __syncthreads();

        // ---- rescale accumulators, then acc += P · V ----
#pragma unroll
        for (int r = 0; r < 4; r++) {
            const float sc = sScale[(ty << 2) + r];
#pragma unroll
            for (int c = 0; c < 4; c++) acc[r][c] *= sc;
        }

#pragma unroll 8
        for (int jj = 0; jj < BN; jj++) {
            const float4 v = *(const float4*)&sV[jj][tx << 2];
            const float p0 = sP[(ty << 2) + 0][jj];
            const float p1 = sP[(ty << 2) + 1][jj];
            const float p2 = sP[(ty << 2) + 2][jj];
            const float p3 = sP[(ty << 2) + 3][jj];
            acc[0][0] = fmaf(p0, v.x, acc[0][0]);
            acc[0][1] = fmaf(p0, v.y, acc[0][1]);
            acc[0][2] = fmaf(p0, v.z, acc[0][2]);
            acc[0][3] = fmaf(p0, v.w, acc[0][3]);
            acc[1][0] = fmaf(p1, v.x, acc[1][0]);
            acc[1][1] = fmaf(p1, v.y, acc[1][1]);
            acc[1][2] = fmaf(p1, v.z, acc[1][2]);
            acc[1][3] = fmaf(p1, v.w, acc[1][3]);
            acc[2][0] = fmaf(p2, v.x, acc[2][0]);
            acc[2][1] = fmaf(p2, v.y, acc[2][1]);
            acc[2][2] = fmaf(p2, v.z, acc[2][2]);
            acc[2][3] = fmaf(p2, v.w, acc[2][3]);
            acc[3][0] = fmaf(p3, v.x, acc[3][0]);
            acc[3][1] = fmaf(p3, v.y, acc[3][1]);
            acc[3][2] = fmaf(p3, v.z, acc[3][2]);
            acc[3][3] = fmaf(p3, v.w, acc[3][3]);
        }

        __syncthreads();
    }

    // ---- epilogue: divide by softmax sum, apply ELU, store ----
#pragma unroll
    for (int r = 0; r < 4; r++) {
        const float inv = 1.0f / sS[(ty << 2) + r];
        const long gi = (long)(b * Nn + i0 + (ty << 2) + r);
        float4 o;
        float x;
        x = acc[r][0] * inv; o.x = (x > 0.f) ? x : expm1f(x);
        x = acc[r][1] * inv; o.y = (x > 0.f) ? x : expm1f(x);
        x = acc[r][2] * inv; o.z = (x > 0.f) ? x : expm1f(x);
        x = acc[r][3] * inv; o.w = (x > 0.f) ? x : expm1f(x);
        *(float4*)&out[gi * FO + (tx << 2)] = o;
    }
}

// ---------------------------------------------------------------------------
extern "C" void kernel_launch(void* const* d_in, const int* in_sizes, int n_in,
                              void* d_out, int out_size)
{
    const float* h   = (const float*)d_in[0];
    const int*   adj = (const int*)d_in[1];
    const float* W   = (const float*)d_in[2];
    const float* a   = (const float*)d_in[3];
    float* out = (float*)d_out;

    gat_proj_kernel<<<(Bsz * Nn) / 16, 256>>>(h, W, a);
    gat_agg_kernel<<<dim3(Nn / BM, Bsz), 256>>>(adj, out);
}

// round 4
// speedup vs baseline: 1.0339x; 1.0339x over previous
#include <cuda_runtime.h>
#include <cstdint>

#define Bsz 8
#define Nn 2048
#define FIN 128
#define FO 64
#define ALPHA 0.2f

#define BM 128
#define BN 32
#define NTILES (Nn / BN)   // 64

// Scratch device globals (allocation-free per harness rules)
__device__ float g_WhT[Bsz * FO * Nn];   // transposed: [b][o][n]
__device__ float g_e1[Bsz * Nn];
__device__ float g_e2[Bsz * Nn];

// ---------------------------------------------------------------------------
// helpers
// ---------------------------------------------------------------------------
static __device__ __forceinline__ float tf32r(float x) {
    uint32_t u;
    asm("cvt.rna.tf32.f32 %0, %1;" : "=r"(u) : "f"(x));
    return __uint_as_float(u);
}

static __device__ __forceinline__ void mma_tf32(
    float* d, const uint32_t* a, uint32_t b0, uint32_t b1)
{
    asm volatile(
        "mma.sync.aligned.m16n8k8.row.col.f32.tf32.tf32.f32 "
        "{%0,%1,%2,%3},{%4,%5,%6,%7},{%8,%9},{%0,%1,%2,%3};"
        : "+f"(d[0]), "+f"(d[1]), "+f"(d[2]), "+f"(d[3])
        : "r"(a[0]), "r"(a[1]), "r"(a[2]), "r"(a[3]), "r"(b0), "r"(b1));
}

// ---------------------------------------------------------------------------
// Kernel 1: Wh = h @ W (written TRANSPOSED as WhT[b][o][n]); e1 = Wh·a1; e2 = Wh·a2
// ---------------------------------------------------------------------------
__global__ __launch_bounds__(256) void gat_proj_kernel(
    const float* __restrict__ h,
    const float* __restrict__ W,
    const float* __restrict__ a)
{
    __shared__ float sW[FIN * FO];        // 32 KB
    __shared__ float sT[FO * 20];         // transpose staging, pitch 20

    const int t = threadIdx.x;
#pragma unroll
    for (int r = 0; r < 8; r++)
        *(float4*)&sW[r * 1024 + t * 4] = *(const float4*)&W[r * 1024 + t * 4];

    const int warp = t >> 5;
    const int lane = t & 31;
    const int g0 = blockIdx.x * 16;
    const int i0 = g0 + warp * 2;

    const float a1l = a[lane];
    const float a1h = a[lane + 32];
    const float a2l = a[FO + lane];
    const float a2h = a[FO + 32 + lane];

    __syncthreads();

    float hr0[4], hr1[4];
    const float* h0p = h + (long)i0 * FIN;
    const float* h1p = h + (long)(i0 + 1) * FIN;
#pragma unroll
    for (int q = 0; q < 4; q++) {
        hr0[q] = h0p[q * 32 + lane];
        hr1[q] = h1p[q * 32 + lane];
    }

    float acc00 = 0.f, acc01 = 0.f, acc10 = 0.f, acc11 = 0.f;
#pragma unroll
    for (int q = 0; q < 4; q++) {
#pragma unroll
        for (int kk = 0; kk < 32; kk++) {
            const int k = q * 32 + kk;
            const float w0 = sW[k * FO + lane];
            const float w1 = sW[k * FO + 32 + lane];
            const float hv0 = __shfl_sync(0xffffffffu, hr0[q], kk);
            const float hv1 = __shfl_sync(0xffffffffu, hr1[q], kk);
            acc00 = fmaf(hv0, w0, acc00);
            acc01 = fmaf(hv0, w1, acc01);
            acc10 = fmaf(hv1, w0, acc10);
            acc11 = fmaf(hv1, w1, acc11);
        }
    }

    const int w2 = warp * 2;
    sT[lane * 20 + w2]            = acc00;
    sT[(lane + 32) * 20 + w2]     = acc01;
    sT[lane * 20 + w2 + 1]        = acc10;
    sT[(lane + 32) * 20 + w2 + 1] = acc11;

    float e1a = acc00 * a1l + acc01 * a1h;
    float e2a = acc00 * a2l + acc01 * a2h;
    float e1b = acc10 * a1l + acc11 * a1h;
    float e2b = acc10 * a2l + acc11 * a2h;
#pragma unroll
    for (int off = 16; off > 0; off >>= 1) {
        e1a += __shfl_xor_sync(0xffffffffu, e1a, off);
        e2a += __shfl_xor_sync(0xffffffffu, e2a, off);
        e1b += __shfl_xor_sync(0xffffffffu, e1b, off);
        e2b += __shfl_xor_sync(0xffffffffu, e2b, off);
    }
    if (lane == 0) {
        g_e1[i0]     = e1a;
        g_e2[i0]     = e2a;
        g_e1[i0 + 1] = e1b;
        g_e2[i0 + 1] = e2b;
    }

    __syncthreads();

    const int bb = g0 >> 11;
    const int il = g0 & (Nn - 1);
    const int o  = t >> 2;
    const int ii = (t & 3) * 4;
    float4 v = *(float4*)&sT[o * 20 + ii];
    *(float4*)&g_WhT[((long)(bb * FO + o)) * Nn + il + ii] = v;
}

// ---------------------------------------------------------------------------
// Kernel 2: masked-softmax aggregation via mma.sync tf32 (no-max softmax).
// grid (16, 8), 256 threads. Double-buffered smem, one sync per j-tile.
// ---------------------------------------------------------------------------
__global__ __launch_bounds__(256, 1) void gat_agg_mma_kernel(
    const int* __restrict__ adj,
    float* __restrict__ out)
{
    // exactly 48 KB static shared
    __shared__ __align__(16) float sP[2][BM * BN];    // 32 KB, swizzled rows of 32 words
    __shared__ __align__(16) float sVT[2][FO * BN];   // 16 KB
    float* sS = &sVT[0][0];   // aliased row-sum array (sVT[0] dead by then)

    const int b  = blockIdx.y;
    const int i0 = blockIdx.x * BM;
    const int t  = threadIdx.x;
    const int warp = t >> 5;
    const int lane = t & 31;

    // score mapping: thread <-> (row, half of 16 j's)
    const int rowi = t >> 1;
    const int jh   = t & 1;
    const float e1i = g_e1[b * Nn + i0 + rowi];
    const int*  adjRow = adj + ((long)(b * Nn + i0 + rowi)) * Nn + jh * 16;
    const float* e2p   = g_e2 + b * Nn + jh * 16;

    // V staging mapping: thread <-> (o, 8 j's)
    const int vo = t >> 2;
    const int vq = (t & 3) * 8;
    const float* vsrc = g_WhT + ((long)(b * FO + vo)) * Nn + vq;

    // matmul mapping: warp tile 32x32: rows mR..mR+31, cols cgBase..cgBase+31
    const int mR     = (warp >> 1) * 32;
    const int cgBase = (warp & 1) * 32;
    const int lq = lane >> 2;   // 0..7
    const int lr = lane & 3;    // 0..3

    float acc[2][4][4];
#pragma unroll
    for (int m = 0; m < 2; m++)
#pragma unroll
        for (int n = 0; n < 4; n++)
#pragma unroll
            for (int r = 0; r < 4; r++) acc[m][n][r] = 0.f;

    float ssum = 0.f;

    for (int tile = 0; tile < NTILES; tile++) {
        const int j0 = tile * BN;
        const int buf = tile & 1;

        // ---- gmem loads (overlap with previous tile's MMAs) ----
        int4 av[4];
        float4 e2v[4];
#pragma unroll
        for (int g = 0; g < 4; g++) {
            av[g]  = *(const int4*)(adjRow + j0 + g * 4);
            e2v[g] = *(const float4*)(e2p + j0 + g * 4);
        }
        const float4 v0 = *(const float4*)(vsrc + j0);
        const float4 v1 = *(const float4*)(vsrc + j0 + 4);

        // ---- scores: p = adj ? tf32(exp(lrelu(e1+e2))) : 0 ; swizzled store ----
        float* sPb = &sP[buf][0];
#pragma unroll
        for (int g = 0; g < 4; g++) {
            float4 p;
            float x;
            x = e1i + e2v[g].x; x = fmaxf(x, ALPHA * x);
            p.x = (av[g].x > 0) ? tf32r(__expf(x)) : 0.f;
            x = e1i + e2v[g].y; x = fmaxf(x, ALPHA * x);
            p.y = (av[g].y > 0) ? tf32r(__expf(x)) : 0.f;
            x = e1i + e2v[g].z; x = fmaxf(x, ALPHA * x);
            p.z = (av[g].z > 0) ? tf32r(__expf(x)) : 0.f;
            x = e1i + e2v[g].w; x = fmaxf(x, ALPHA * x);
            p.w = (av[g].w > 0) ? tf32r(__expf(x)) : 0.f;
            ssum += (p.x + p.y) + (p.z + p.w);
            const int c = jh * 16 + g * 4;
            const int w = (rowi << 5) + ((c + (rowi << 2)) & 31);
            *(float4*)(sPb + w) = p;
        }
        // ---- V tile store (XOR swizzle) ----
        {
            float* sVb = &sVT[buf][0];
            const int s  = (vo & 7) << 2;
            *(float4*)(sVb + (vo << 5) + (vq ^ s))       = v0;
            *(float4*)(sVb + (vo << 5) + ((vq + 4) ^ s)) = v1;
        }

        __syncthreads();

        // ---- matmul: 2m x 4n x 4k  m16n8k8 tf32 ----
        const float* cPb = &sP[buf][0];
        const float* cVb = &sVT[buf][0];
#pragma unroll
        for (int k = 0; k < 4; k++) {
            uint32_t a[2][4];
#pragma unroll
            for (int m = 0; m < 2; m++) {
                const int r0 = mR + m * 16 + lq;
                const int r1 = r0 + 8;
                const int c0 = k * 8 + lr;
                a[m][0] = __float_as_uint(cPb[(r0 << 5) + ((c0 + (r0 << 2)) & 31)]);
                a[m][1] = __float_as_uint(cPb[(r1 << 5) + ((c0 + (r1 << 2)) & 31)]);
                a[m][2] = __float_as_uint(cPb[(r0 << 5) + ((c0 + 4 + (r0 << 2)) & 31)]);
                a[m][3] = __float_as_uint(cPb[(r1 << 5) + ((c0 + 4 + (r1 << 2)) & 31)]);
            }
#pragma unroll
            for (int nt = 0; nt < 4; nt++) {
                const int o = cgBase + nt * 8 + lq;
                const int s = (o & 7) << 2;
                const int jb = k * 8 + lr;
                const uint32_t b0 = __float_as_uint(cVb[(o << 5) + (jb ^ s)]);
                const uint32_t b1 = __float_as_uint(cVb[(o << 5) + ((jb + 4) ^ s)]);
                mma_tf32(acc[0][nt], a[0], b0, b1);
                mma_tf32(acc[1][nt], a[1], b0, b1);
            }
        }
    }

    // ---- row sums: combine the two half-row threads (adjacent lanes) ----
    ssum += __shfl_xor_sync(0xffffffffu, ssum, 1);
    if (jh == 0) sS[rowi] = ssum;    // sVT[0] no longer read (last tile used buf 1)
    __syncthreads();

    // ---- epilogue: normalize, ELU, store ----
#pragma unroll
    for (int m = 0; m < 2; m++) {
        const int r0 = mR + m * 16 + lq;
        const int r1 = r0 + 8;
        const float inv0 = 1.0f / sS[r0];
        const float inv1 = 1.0f / sS[r1];
        float* o0 = out + ((long)(b * Nn + i0 + r0)) * FO;
        float* o1 = out + ((long)(b * Nn + i0 + r1)) * FO;
#pragma unroll
        for (int nt = 0; nt < 4; nt++) {
            const int col = cgBase + nt * 8 + lr * 2;
            float2 q0, q1;
            float x;
            x = acc[m][nt][0] * inv0; q0.x = (x > 0.f) ? x : expm1f(x);
            x = acc[m][nt][1] * inv0; q0.y = (x > 0.f) ? x : expm1f(x);
            x = acc[m][nt][2] * inv1; q1.x = (x > 0.f) ? x : expm1f(x);
            x = acc[m][nt][3] * inv1; q1.y = (x > 0.f) ? x : expm1f(x);
            *(float2*)(o0 + col) = q0;
            *(float2*)(o1 + col) = q1;
        }
    }
}

// ---------------------------------------------------------------------------
extern "C" void kernel_launch(void* const* d_in, const int* in_sizes, int n_in,
                              void* d_out, int out_size)
{
    const float* h   = (const float*)d_in[0];
    const int*   adj = (const int*)d_in[1];
    const float* W   = (const float*)d_in[2];
    const float* a   = (const float*)d_in[3];
    float* out = (float*)d_out;

    gat_proj_kernel<<<(Bsz * Nn) / 16, 256>>>(h, W, a);
    gat_agg_mma_kernel<<<dim3(Nn / BM, Bsz), 256>>>(adj, out);
}

// round 7
// speedup vs baseline: 1.1770x; 1.1384x over previous
#include <cuda_runtime.h>
#include <cstdint>

#define Bsz 8
#define Nn 2048
#define FIN 128
#define FO 64
#define ALPHA 0.2f

#define BM 32
#define BN 32
#define NTILES (Nn / BN)   // 64

// Scratch device globals (allocation-free per harness rules)
__device__ float g_WhT[Bsz * FO * Nn];   // transposed: [b][o][n]
__device__ float g_e1[Bsz * Nn];
__device__ float g_e2[Bsz * Nn];

// ---------------------------------------------------------------------------
// helpers
// ---------------------------------------------------------------------------
static __device__ __forceinline__ float tf32r(float x) {
    uint32_t u;
    asm("cvt.rna.tf32.f32 %0, %1;" : "=r"(u) : "f"(x));
    return __uint_as_float(u);
}

static __device__ __forceinline__ void mma_tf32(
    float* d, const uint32_t* a, uint32_t b0, uint32_t b1)
{
    asm volatile(
        "mma.sync.aligned.m16n8k8.row.col.f32.tf32.tf32.f32 "
        "{%0,%1,%2,%3},{%4,%5,%6,%7},{%8,%9},{%0,%1,%2,%3};"
        : "+f"(d[0]), "+f"(d[1]), "+f"(d[2]), "+f"(d[3])
        : "r"(a[0]), "r"(a[1]), "r"(a[2]), "r"(a[3]), "r"(b0), "r"(b1));
}

// ---------------------------------------------------------------------------
// Kernel 1: Wh = h @ W (written TRANSPOSED as WhT[b][o][n]); e1 = Wh·a1; e2 = Wh·a2
// 512 blocks x 256 threads; 32 rows per block, 4 rows per warp.
// ---------------------------------------------------------------------------
__global__ __launch_bounds__(256) void gat_proj_kernel(
    const float* __restrict__ h,
    const float* __restrict__ W,
    const float* __restrict__ a)
{
    __shared__ float sW[FIN * FO];   // 32 KB
    __shared__ float sT[FO * 33];    // transpose staging, pitch 33 (conflict-free)

    const int t = threadIdx.x;
#pragma unroll
    for (int r = 0; r < 8; r++)
        *(float4*)&sW[r * 1024 + t * 4] = *(const float4*)&W[r * 1024 + t * 4];

    const int warp = t >> 5;
    const int lane = t & 31;
    const int g0 = blockIdx.x * 32;
    const int i0 = g0 + warp * 4;

    const float a1l = a[lane];
    const float a1h = a[lane + 32];
    const float a2l = a[FO + lane];
    const float a2h = a[FO + 32 + lane];

    __syncthreads();

    float hr[4][4];
#pragma unroll
    for (int r = 0; r < 4; r++) {
        const float* hp = h + (long)(i0 + r) * FIN;
#pragma unroll
        for (int q = 0; q < 4; q++) hr[r][q] = hp[q * 32 + lane];
    }

    float acc[4][2];
#pragma unroll
    for (int r = 0; r < 4; r++) { acc[r][0] = 0.f; acc[r][1] = 0.f; }

#pragma unroll
    for (int q = 0; q < 4; q++) {
#pragma unroll
        for (int kk = 0; kk < 32; kk++) {
            const int k = q * 32 + kk;
            const float w0 = sW[k * FO + lane];
            const float w1 = sW[k * FO + 32 + lane];
#pragma unroll
            for (int r = 0; r < 4; r++) {
                const float hv = __shfl_sync(0xffffffffu, hr[r][q], kk);
                acc[r][0] = fmaf(hv, w0, acc[r][0]);
                acc[r][1] = fmaf(hv, w1, acc[r][1]);
            }
        }
    }

    // stage transposed: sT[o][i_local], pitch 33
#pragma unroll
    for (int r = 0; r < 4; r++) {
        sT[lane * 33 + warp * 4 + r]        = acc[r][0];
        sT[(lane + 32) * 33 + warp * 4 + r] = acc[r][1];
    }

    // e1/e2 warp reductions (4 rows)
#pragma unroll
    for (int r = 0; r < 4; r++) {
        float e1 = acc[r][0] * a1l + acc[r][1] * a1h;
        float e2 = acc[r][0] * a2l + acc[r][1] * a2h;
#pragma unroll
        for (int off = 16; off > 0; off >>= 1) {
            e1 += __shfl_xor_sync(0xffffffffu, e1, off);
            e2 += __shfl_xor_sync(0xffffffffu, e2, off);
        }
        if (lane == 0) {
            g_e1[i0 + r] = e1;
            g_e2[i0 + r] = e2;
        }
    }

    __syncthreads();

    // transposed write: WhT[b][o][n] (scalar LDS -> STG.128, conflict-free)
    const int bb = g0 >> 11;
    const int il = g0 & (Nn - 1);
    const int oB = t >> 3;
    const int ii = (t & 7) * 4;
#pragma unroll
    for (int hf = 0; hf < 2; hf++) {
        const int o = hf * 32 + oB;
        float4 v;
        v.x = sT[o * 33 + ii + 0];
        v.y = sT[o * 33 + ii + 1];
        v.z = sT[o * 33 + ii + 2];
        v.w = sT[o * 33 + ii + 3];
        *(float4*)&g_WhT[((long)(bb * FO + o)) * Nn + il + ii] = v;
    }
}

// ---------------------------------------------------------------------------
// Kernel 2: masked-softmax aggregation via mma.sync tf32 (no-max softmax).
// grid (64, 8) = 512 CTAs, 256 threads. Double-buffered smem, one sync/tile,
// register prefetch of next tile's gmem overlapping the MMA phase.
// ---------------------------------------------------------------------------
__global__ __launch_bounds__(256) void gat_agg_mma_kernel(
    const int* __restrict__ adj,
    float* __restrict__ out)
{
    __shared__ __align__(16) float sP[2][BM * BN];    // 8 KB
    __shared__ __align__(16) float sVT[2][FO * BN];   // 16 KB
    __shared__ float sS[BM];

    const int b  = blockIdx.y;
    const int i0 = blockIdx.x * BM;
    const int t  = threadIdx.x;
    const int warp = t >> 5;
    const int lane = t & 31;

    // score mapping: thread <-> (row, 4 j's)
    const int rowi = t >> 3;            // 0..31
    const int jq   = (t & 7) * 4;       // 0..28
    const float e1i = g_e1[b * Nn + i0 + rowi];
    const int*   adjRow = adj + ((long)(b * Nn + i0 + rowi)) * Nn + jq;
    const float* e2p    = g_e2 + b * Nn + jq;

    // V staging mapping: thread <-> (o, 8 j's)
    const int vo = t >> 2;
    const int vq = (t & 3) * 8;
    const float* vsrc = g_WhT + ((long)(b * FO + vo)) * Nn + vq;

    // matmul mapping: warp tile 16 rows x 16 cols
    const int wm = warp & 1;            // row group (16 rows)
    const int wn = warp >> 1;           // col group (16 cols), 0..3
    const int lq = lane >> 2;           // 0..7
    const int lr = lane & 3;            // 0..3

    float acc[2][4];
#pragma unroll
    for (int n = 0; n < 2; n++)
#pragma unroll
        for (int r = 0; r < 4; r++) acc[n][r] = 0.f;

    // prologue: preload tile 0
    int4   av  = *(const int4*)(adjRow);
    float4 e2v = *(const float4*)(e2p);
    float4 v0  = *(const float4*)(vsrc);
    float4 v1  = *(const float4*)(vsrc + 4);

    float ssum = 0.f;

    for (int tile = 0; tile < NTILES; tile++) {
        const int buf = tile & 1;

        // ---- scores: p = adj ? tf32(exp(lrelu(e1+e2))) : 0 ----
        float4 p;
        float x;
        x = e1i + e2v.x; x = fmaxf(x, ALPHA * x);
        p.x = (av.x > 0) ? tf32r(__expf(x)) : 0.f;
        x = e1i + e2v.y; x = fmaxf(x, ALPHA * x);
        p.y = (av.y > 0) ? tf32r(__expf(x)) : 0.f;
        x = e1i + e2v.z; x = fmaxf(x, ALPHA * x);
        p.z = (av.z > 0) ? tf32r(__expf(x)) : 0.f;
        x = e1i + e2v.w; x = fmaxf(x, ALPHA * x);
        p.w = (av.w > 0) ? tf32r(__expf(x)) : 0.f;
        ssum += (p.x + p.y) + (p.z + p.w);

        // swizzled P store: word = (row<<5) + ((c + 4*row)&31)
        *(float4*)&sP[buf][(rowi << 5) + ((jq + (rowi << 2)) & 31)] = p;

        // V tile store (XOR swizzle)
        {
            const int s = (vo & 7) << 2;
            *(float4*)&sVT[buf][(vo << 5) + (vq ^ s)]       = v0;
            *(float4*)&sVT[buf][(vo << 5) + ((vq + 4) ^ s)] = v1;
        }

        __syncthreads();

        // ---- prefetch next tile's gmem (overlaps MMA below) ----
        if (tile < NTILES - 1) {
            const int j0n = (tile + 1) * BN;
            av  = *(const int4*)(adjRow + j0n);
            e2v = *(const float4*)(e2p + j0n);
            v0  = *(const float4*)(vsrc + j0n);
            v1  = *(const float4*)(vsrc + j0n + 4);
        }

        // ---- matmul: 1m x 2n x 4k  m16n8k8 tf32 ----
        const float* cP = &sP[buf][0];
        const float* cV = &sVT[buf][0];
#pragma unroll
        for (int k = 0; k < 4; k++) {
            uint32_t a[4];
            const int r0 = wm * 16 + lq;
            const int r1 = r0 + 8;
            const int c0 = k * 8 + lr;
            a[0] = __float_as_uint(cP[(r0 << 5) + ((c0 + (r0 << 2)) & 31)]);
            a[1] = __float_as_uint(cP[(r1 << 5) + ((c0 + (r1 << 2)) & 31)]);
            a[2] = __float_as_uint(cP[(r0 << 5) + ((c0 + 4 + (r0 << 2)) & 31)]);
            a[3] = __float_as_uint(cP[(r1 << 5) + ((c0 + 4 + (r1 << 2)) & 31)]);
#pragma unroll
            for (int nt = 0; nt < 2; nt++) {
                const int o = wn * 16 + nt * 8 + lq;
                const int s = (o & 7) << 2;
                const int jb = k * 8 + lr;
                const uint32_t b0 = __float_as_uint(cV[(o << 5) + (jb ^ s)]);
                const uint32_t b1 = __float_as_uint(cV[(o << 5) + ((jb + 4) ^ s)]);
                mma_tf32(acc[nt], a, b0, b1);
            }
        }
    }

    // ---- row sums: reduce over the 8 threads sharing a row ----
    ssum += __shfl_xor_sync(0xffffffffu, ssum, 1);
    ssum += __shfl_xor_sync(0xffffffffu, ssum, 2);
    ssum += __shfl_xor_sync(0xffffffffu, ssum, 4);
    if ((t & 7) == 0) sS[rowi] = ssum;
    __syncthreads();

    // ---- epilogue: normalize, ELU, store ----
    {
        const int r0 = wm * 16 + lq;
        const int r1 = r0 + 8;
        const float inv0 = 1.0f / sS[r0];
        const float inv1 = 1.0f / sS[r1];
        float* o0 = out + ((long)(b * Nn + i0 + r0)) * FO;
        float* o1 = out + ((long)(b * Nn + i0 + r1)) * FO;
#pragma unroll
        for (int nt = 0; nt < 2; nt++) {
            const int col = wn * 16 + nt * 8 + lr * 2;
            float2 q0, q1;
            float x;
            x = acc[nt][0] * inv0; q0.x = (x > 0.f) ? x : expm1f(x);
            x = acc[nt][1] * inv0; q0.y = (x > 0.f) ? x : expm1f(x);
            x = acc[nt][2] * inv1; q1.x = (x > 0.f) ? x : expm1f(x);
            x = acc[nt][3] * inv1; q1.y = (x > 0.f) ? x : expm1f(x);
            *(float2*)(o0 + col) = q0;
            *(float2*)(o1 + col) = q1;
        }
    }
}

// ---------------------------------------------------------------------------
extern "C" void kernel_launch(void* const* d_in, const int* in_sizes, int n_in,
                              void* d_out, int out_size)
{
    const float* h   = (const float*)d_in[0];
    const int*   adj = (const int*)d_in[1];
    const float* W   = (const float*)d_in[2];
    const float* a   = (const float*)d_in[3];
    float* out = (float*)d_out;

    gat_proj_kernel<<<(Bsz * Nn) / 32, 256>>>(h, W, a);
    gat_agg_mma_kernel<<<dim3(Nn / BM, Bsz), 256>>>(adj, out);
}